// round 1
// baseline (speedup 1.0000x reference)
#include <cuda_runtime.h>
#include <cstdint>

#define B   256
#define T   1024
#define H   256
#define INP 32
#define OUTD 32
#define G3  768
#define NC  128   // persistent CTAs (all resident: NC <= SM count)

// Static device scratch (allocation-free rule)
__device__ float g_obsT[(size_t)T * INP * B];     // [t][i][b]   33.5 MB
__device__ float g_Hst[(size_t)(T + 1) * H * B];  // [t][h][b]   268.7 MB, t=0 stays zero (BSS)
__device__ float g_M[4 * H * H];                  // merged recurrent matrix [g*256+hc][k]
__device__ float g_C[G3 * B];                     // per-(gate,b) constants, t>=1
__device__ float g_C0[G3 * B];                    // per-(gate,b) constants, t==0
__device__ unsigned g_cnt;                        // barrier arrive counter
__device__ unsigned g_epoch;                      // barrier release epoch

typedef unsigned long long u64;

__device__ __forceinline__ u64 pack2(float x, float y) {
    u64 r; asm("mov.b64 %0,{%1,%2};" : "=l"(r) : "f"(x), "f"(y)); return r;
}
__device__ __forceinline__ void unpack2(u64 v, float& x, float& y) {
    asm("mov.b64 {%0,%1},%2;" : "=f"(x), "=f"(y) : "l"(v));
}
// packed 2x fp32 FMA (sm_100+ f32x2 pipe: 2x FFMA throughput)
__device__ __forceinline__ u64 fma2(u64 a, u64 b, u64 c) {
    u64 d; asm("fma.rn.f32x2 %0,%1,%2,%3;" : "=l"(d) : "l"(a), "l"(b), "l"(c)); return d;
}

__device__ __forceinline__ float sigf(float x) {
    return __fdividef(1.0f, 1.0f + __expf(-x));
}
__device__ __forceinline__ float tanhx(float x) {
    // tanh(x) = 2/(1+exp(-2x)) - 1 ; saturates correctly at +-1 via inf/0
    return __fdividef(2.0f, 1.0f + __expf(-2.0f * x)) - 1.0f;
}

// ---------------------------------------------------------------------------
// obs (B,T,INP) -> obsT [t][i][b]  (coalesced writes)
__global__ void k_transpose(const float* __restrict__ obs) {
    int t = blockIdx.x, b = threadIdx.x;
    const float4* src = (const float4*)(obs + (size_t)b * T * INP + (size_t)t * INP);
    float4 v[8];
#pragma unroll
    for (int q = 0; q < 8; q++) v[q] = src[q];
    float* dst = g_obsT + (size_t)t * (INP * B) + b;
#pragma unroll
    for (int q = 0; q < 8; q++) {
        dst[(4 * q + 0) * B] = v[q].x;
        dst[(4 * q + 1) * B] = v[q].y;
        dst[(4 * q + 2) * B] = v[q].z;
        dst[(4 * q + 3) * B] = v[q].w;
    }
}

// ---------------------------------------------------------------------------
// Build merged recurrent matrix M (1024 x 256):
//   rows [0,512):   W_hh[j] + W_comb[j]            (r, z merged)
//   rows [512,768): W_comb[j]                      (xn: h-part of gx_n)
//   rows [768,1024): W_hh[j-256]                   (hn)
// where W_comb[j,k] = sum_o W_ih[j, 32+o] * W_out[o, k]
__global__ void k_prep_M(const float* __restrict__ W_ih,
                         const float* __restrict__ W_hh,
                         const float* __restrict__ W_out) {
    int j = blockIdx.x, k = threadIdx.x;
    float v;
    if (j < 768) {
        float comb = 0.f;
#pragma unroll
        for (int o = 0; o < 32; o++)
            comb = fmaf(W_ih[j * 96 + 32 + o], W_out[o * H + k], comb);
        v = (j < 512) ? (W_hh[j * H + k] + comb) : comb;
    } else {
        v = W_hh[(j - 256) * H + k];
    }
    g_M[j * H + k] = v;
}

// ---------------------------------------------------------------------------
// Constants per (gate row j, batch b):
//   C[j][b]  = z_dyn[b].Wz_j + b_ih[j] + (j<512 ? b_hh[j] : 0) + b_out.Wy_j   (t>=1)
//   C0[j][b] = z_dyn[b].Wz_j + b_ih[j] + (j<512 ? b_hh[j] : 0) + init_y[b].Wy_j (t==0)
__global__ void k_prep_C(const float* __restrict__ z_dyn,
                         const float* __restrict__ init_y,
                         const float* __restrict__ W_ih,
                         const float* __restrict__ b_ih,
                         const float* __restrict__ b_hh,
                         const float* __restrict__ b_out) {
    int j = blockIdx.x, b = threadIdx.x;
    float zp = 0.f, yb = 0.f, iy = 0.f;
#pragma unroll
    for (int i = 0; i < 32; i++)
        zp = fmaf(z_dyn[b * 32 + i], W_ih[j * 96 + 64 + i], zp);
#pragma unroll
    for (int o = 0; o < 32; o++) {
        float wy = W_ih[j * 96 + 32 + o];
        yb = fmaf(b_out[o], wy, yb);
        iy = fmaf(init_y[b * 32 + o], wy, iy);
    }
    float base = b_ih[j] + (j < 512 ? b_hh[j] : 0.f);
    g_C[j * B + b]  = zp + base + yb;
    g_C0[j * B + b] = zp + base + iy;
}

// ---------------------------------------------------------------------------
// Persistent sequential GRU loop. CTA c owns h-columns {2c, 2c+1}.
__global__ void __launch_bounds__(256, 1)
k_rnn(const float* __restrict__ W_ih, const float* __restrict__ b_hh) {
    __shared__ __align__(16) u64 m2_s[4][H];    // merged M slice (pairs over 2 h-cols)
    __shared__ u64 c2_s[3][B];
    __shared__ u64 c02_s[3][B];
    __shared__ u64 wobs2_s[3][INP];

    const int c = blockIdx.x, tid = threadIdx.x;
    const int hc0 = 2 * c, hc1 = 2 * c + 1;

#pragma unroll
    for (int g = 0; g < 4; g++)
        m2_s[g][tid] = pack2(g_M[(g * H + hc0) * H + tid], g_M[(g * H + hc1) * H + tid]);
#pragma unroll
    for (int g = 0; g < 3; g++) {
        c2_s[g][tid]  = pack2(g_C[(g * H + hc0) * B + tid],  g_C[(g * H + hc1) * B + tid]);
        c02_s[g][tid] = pack2(g_C0[(g * H + hc0) * B + tid], g_C0[(g * H + hc1) * B + tid]);
    }
    if (tid < INP) {
#pragma unroll
        for (int g = 0; g < 3; g++)
            wobs2_s[g][tid] = pack2(W_ih[(g * H + hc0) * 96 + tid],
                                    W_ih[(g * H + hc1) * 96 + tid]);
    }
    const u64 bhh2 = pack2(b_hh[2 * H + hc0], b_hh[2 * H + hc1]);
    __syncthreads();

    unsigned ep = *(volatile unsigned*)&g_epoch;  // stable: no release until all CTAs arrive
    float hp0 = 0.f, hp1 = 0.f;
    const int b = tid;

    for (int t = 0; t < T; t++) {
        const u64* cs = (t == 0) ? &c02_s[0][0] : &c2_s[0][0];
        u64 aR = cs[0 * B + b], aZ = cs[1 * B + b], aXN = cs[2 * B + b], aHN = bhh2;

        // obs_t contribution (obsT resident in L2 within the step)
        const float* op = g_obsT + (size_t)t * (INP * B) + b;
#pragma unroll 8
        for (int i = 0; i < INP; i++) {
            float ov = op[i * B];
            u64 ov2 = pack2(ov, ov);
            aR  = fma2(ov2, wobs2_s[0][i], aR);
            aZ  = fma2(ov2, wobs2_s[1][i], aZ);
            aXN = fma2(ov2, wobs2_s[2][i], aXN);
        }

        // recurrent GEMM: G = h_{t-1} @ M^T  (read Hst[t], L2-hot)
        const float* hs = g_Hst + (size_t)t * (H * B) + b;
#pragma unroll 4
        for (int k = 0; k < H; k += 2) {
            float hva = hs[k * B], hvb = hs[(k + 1) * B];
            u64 ha = pack2(hva, hva), hb = pack2(hvb, hvb);
            ulonglong2 m0 = *(const ulonglong2*)&m2_s[0][k];
            ulonglong2 m1 = *(const ulonglong2*)&m2_s[1][k];
            ulonglong2 mx = *(const ulonglong2*)&m2_s[2][k];
            ulonglong2 m3 = *(const ulonglong2*)&m2_s[3][k];
            aR  = fma2(ha, m0.x, aR);  aR  = fma2(hb, m0.y, aR);
            aZ  = fma2(ha, m1.x, aZ);  aZ  = fma2(hb, m1.y, aZ);
            aXN = fma2(ha, mx.x, aXN); aXN = fma2(hb, mx.y, aXN);
            aHN = fma2(ha, m3.x, aHN); aHN = fma2(hb, m3.y, aHN);
        }

        float xr0, xr1, xz0, xz1, xn0, xn1, hn0, hn1;
        unpack2(aR, xr0, xr1); unpack2(aZ, xz0, xz1);
        unpack2(aXN, xn0, xn1); unpack2(aHN, hn0, hn1);
        float r0 = sigf(xr0), r1 = sigf(xr1);
        float z0 = sigf(xz0), z1 = sigf(xz1);
        float n0 = tanhx(fmaf(r0, hn0, xn0));
        float n1 = tanhx(fmaf(r1, hn1, xn1));
        float h0 = fmaf(z0, hp0 - n0, n0);   // (1-z)*n + z*h
        float h1 = fmaf(z1, hp1 - n1, n1);

        float* hd = g_Hst + (size_t)(t + 1) * (H * B);
        hd[hc0 * B + b] = h0;
        hd[hc1 * B + b] = h1;
        hp0 = h0; hp1 = h1;

        // ---- grid barrier (all NC CTAs resident; release-epoch protocol) ----
        __threadfence();
        __syncthreads();
        ep++;
        if (tid == 0) {
            unsigned prev = atomicAdd(&g_cnt, 1u);
            if (prev == NC - 1) {
                g_cnt = 0u;
                __threadfence();
                atomicExch(&g_epoch, ep);
            } else {
                while ((int)(*(volatile unsigned*)&g_epoch - ep) < 0) __nanosleep(32);
                __threadfence();
            }
        }
        __syncthreads();
    }
}

// ---------------------------------------------------------------------------
// y[b,t,:] = h_t @ W_out^T + b_out   (parallel epilogue over all t)
__global__ void __launch_bounds__(256)
k_out(const float* __restrict__ W_out, const float* __restrict__ b_out,
      float* __restrict__ out) {
    __shared__ u64 w2[16][H];
    int t = blockIdx.x, b = threadIdx.x;
#pragma unroll
    for (int p = 0; p < 16; p++)
        w2[p][b] = pack2(W_out[(2 * p) * H + b], W_out[(2 * p + 1) * H + b]);
    __syncthreads();

    u64 acc[16];
#pragma unroll
    for (int p = 0; p < 16; p++) acc[p] = pack2(b_out[2 * p], b_out[2 * p + 1]);

    const float* hs = g_Hst + (size_t)(t + 1) * (H * B) + b;
#pragma unroll 4
    for (int h = 0; h < H; h++) {
        float hv = hs[h * B];
        u64 hv2 = pack2(hv, hv);
#pragma unroll
        for (int p = 0; p < 16; p++) acc[p] = fma2(hv2, w2[p][h], acc[p]);
    }
    float* o = out + (size_t)b * (T * OUTD) + (size_t)t * OUTD;
#pragma unroll
    for (int p = 0; p < 16; p++) {
        float x, y; unpack2(acc[p], x, y);
        o[2 * p] = x; o[2 * p + 1] = y;
    }
}

// ---------------------------------------------------------------------------
extern "C" void kernel_launch(void* const* d_in, const int* in_sizes, int n_in,
                              void* d_out, int out_size) {
    const float* init_y = (const float*)d_in[0];
    const float* obs    = (const float*)d_in[1];
    const float* z_dyn  = (const float*)d_in[2];
    const float* W_ih   = (const float*)d_in[3];
    const float* W_hh   = (const float*)d_in[4];
    const float* b_ih   = (const float*)d_in[5];
    const float* b_hh   = (const float*)d_in[6];
    const float* W_out  = (const float*)d_in[7];
    const float* b_out  = (const float*)d_in[8];
    float* out = (float*)d_out;

    k_transpose<<<T, B>>>(obs);
    k_prep_M<<<1024, H>>>(W_ih, W_hh, W_out);
    k_prep_C<<<G3, B>>>(z_dyn, init_y, W_ih, b_ih, b_hh, b_out);
    k_rnn<<<NC, B>>>(W_ih, b_hh);
    k_out<<<T, B>>>(W_out, b_out, out);
}